// round 10
// baseline (speedup 1.0000x reference)
#include <cuda_runtime.h>
#include <cuda_fp16.h>

#define BATCH 128
#define NTF 1024
#define NGENES 20000
#define NPAIRS (NGENES / 2)      // 10000 gene-pairs
#define NEDGE1 (NGENES * 64)     // 1,280,000 layer-1 edges
#define NW2 (NGENES * 16)        // 320,000 layer-2 weights
#define CHUNK 64                 // batch elements per block
#define THREADS 1024             // 32 warps
#define GRID 148                 // one wave, 74 blocks per chunk
#define WARPS_PER_CHUNK 2368     // 74 blocks * 32 warps
#define SMEM_BYTES (NTF * CHUNK * 2)  // 131072

// device scratch
__device__ __half g_xTh[NTF * BATCH];        // transposed fp16 features
__device__ unsigned short g_i16[NEDGE1];     // u16 edge indices
__device__ __half g_w1h[NEDGE1];             // fp16 layer-1 weights
__device__ __half g_w2h[NW2];                // fp16 layer-2 weights
__device__ float  g_yT[NGENES * BATCH];      // gene-major output

__device__ __forceinline__ unsigned int packh2(float a, float b) {
    const __half2 h = __float22half2_rn(make_float2(a, b));
    return *reinterpret_cast<const unsigned int*>(&h);
}
__device__ __forceinline__ unsigned int pack16(int a, int b) {
    return (unsigned int)a | ((unsigned int)b << 16);
}

// ---- prep 1: edge tables (i16 + fp16 w1), 8 edges/thread, 625 blocks ----
__global__ void prep_edges(const int* __restrict__ in1,
                           const float* __restrict__ w1) {
    const int e = (blockIdx.x * 256 + threadIdx.x) * 8;
    const int4 i0 = __ldg((const int4*)(in1 + e));
    const int4 i1 = __ldg((const int4*)(in1 + e) + 1);
    const float4 a0 = __ldg((const float4*)(w1 + e));
    const float4 a1 = __ldg((const float4*)(w1 + e) + 1);
    uint4 iv, wv;
    iv.x = pack16(i0.x, i0.y); iv.y = pack16(i0.z, i0.w);
    iv.z = pack16(i1.x, i1.y); iv.w = pack16(i1.z, i1.w);
    wv.x = packh2(a0.x, a0.y); wv.y = packh2(a0.z, a0.w);
    wv.z = packh2(a1.x, a1.y); wv.w = packh2(a1.z, a1.w);
    *(uint4*)(g_i16 + e) = iv;
    *(uint4*)(g_w1h + e) = wv;
}

// ---- prep 2: [0,128) feature transpose->fp16; [128,285) w2->fp16 ----
__global__ void prep_feat(const float* __restrict__ f,
                          const float* __restrict__ w2) {
    const int bid = blockIdx.x;
    if (bid < 128) {
        __shared__ float tile[32][33];
        const int tx = threadIdx.x & 31, ty = threadIdx.x >> 5;
        const int t0 = (bid & 31) * 32;   // TF base
        const int b0 = (bid >> 5) * 32;   // batch base
#pragma unroll
        for (int j = 0; j < 32; j += 8)
            tile[ty + j][tx] = f[(b0 + ty + j) * NTF + t0 + tx];
        __syncthreads();
#pragma unroll
        for (int j = 0; j < 32; j += 8)
            g_xTh[(t0 + ty + j) * BATCH + b0 + tx] = __float2half(tile[tx][ty + j]);
    } else {
        const int e = ((bid - 128) * 256 + threadIdx.x) * 8;
        if (e < NW2) {
            const float4 a0 = __ldg((const float4*)(w2 + e));
            const float4 a1 = __ldg((const float4*)(w2 + e) + 1);
            uint4 wv;
            wv.x = packh2(a0.x, a0.y); wv.y = packh2(a0.z, a0.w);
            wv.z = packh2(a1.x, a1.y); wv.w = packh2(a1.z, a1.w);
            *(uint4*)(g_w2h + e) = wv;
        }
    }
}

// ---- output transpose: 80-gene x 64-batch tiles, float4 both sides ----
#define TG 80   // genes per tile (20000 / 80 = 250 tiles per batch-half)
#define TB 64   // batches per tile (128 / 64 = 2)
__global__ void transpose_out(float* __restrict__ out) {
    __shared__ float tile[TG][TB + 1];
    const int tid = threadIdx.x;                 // 256 threads
    const int g0 = (blockIdx.x >> 1) * TG;
    const int b0 = (blockIdx.x & 1) * TB;
    // load: 80 gene-rows x 64 batches = 1280 float4, 5 per thread
#pragma unroll
    for (int i = tid; i < TG * (TB / 4); i += 256) {
        const int gr = i / (TB / 4);             // 0..79
        const int bc = i % (TB / 4);             // 0..15
        const float4 v = *(const float4*)&g_yT[(size_t)(g0 + gr) * BATCH + b0 + bc * 4];
        tile[gr][bc * 4 + 0] = v.x;
        tile[gr][bc * 4 + 1] = v.y;
        tile[gr][bc * 4 + 2] = v.z;
        tile[gr][bc * 4 + 3] = v.w;
    }
    __syncthreads();
    // store: 64 batch-rows x 80 genes = 1280 float4, 5 per thread
#pragma unroll
    for (int i = tid; i < TB * (TG / 4); i += 256) {
        const int br = i / (TG / 4);             // 0..63
        const int gc = i % (TG / 4);             // 0..19
        float4 v;
        v.x = tile[gc * 4 + 0][br];
        v.y = tile[gc * 4 + 1][br];
        v.z = tile[gc * 4 + 2][br];
        v.w = tile[gc * 4 + 3][br];
        *(float4*)&out[(size_t)(b0 + br) * NGENES + g0 + gc * 4] = v;
    }
}

__device__ __forceinline__ __half2 u2h(unsigned int u) {
    return *reinterpret_cast<__half2*>(&u);
}
__device__ __forceinline__ float tanh_mufu(float x) {
    float y;
    asm("tanh.approx.f32 %0, %1;" : "=f"(y) : "f"(x));
    return y;
}
__device__ __forceinline__ __half2 tanh_h2(float2 a) {
    __half2 h = __float22half2_rn(a);
    unsigned int u = *reinterpret_cast<unsigned int*>(&h), r;
    asm("tanh.approx.f16x2 %0, %1;" : "=r"(r) : "r"(u));
    return u2h(r);
}

// 4 edges (2 packed index words), LDS.64 row gathers, fp16 chain, fp32 acc
__device__ __forceinline__ void edge_group(const char* fb, unsigned int e01,
                                           unsigned int e23, unsigned int wlo,
                                           unsigned int whi, float4& acc) {
    const uint2 x0 = *(const uint2*)(fb + ((e01 & 0xFFFFu) << 7));
    const uint2 x1 = *(const uint2*)(fb + ((e01 >> 16) << 7));
    const uint2 x2 = *(const uint2*)(fb + ((e23 & 0xFFFFu) << 7));
    const uint2 x3 = *(const uint2*)(fb + ((e23 >> 16) << 7));
    __half2 alo = __hmul2(__low2half2(u2h(wlo)),  u2h(x0.x));
    __half2 ahi = __hmul2(__low2half2(u2h(wlo)),  u2h(x0.y));
    alo = __hfma2(__high2half2(u2h(wlo)), u2h(x1.x), alo);
    ahi = __hfma2(__high2half2(u2h(wlo)), u2h(x1.y), ahi);
    alo = __hfma2(__low2half2(u2h(whi)),  u2h(x2.x), alo);
    ahi = __hfma2(__low2half2(u2h(whi)),  u2h(x2.y), ahi);
    alo = __hfma2(__high2half2(u2h(whi)), u2h(x3.x), alo);
    ahi = __hfma2(__high2half2(u2h(whi)), u2h(x3.y), ahi);
    const float2 flo = __half22float2(alo);
    const float2 fhi = __half22float2(ahi);
    acc.x += flo.x; acc.y += flo.y; acc.z += fhi.x; acc.w += fhi.y;
}

// layer-2 node (fp16 MAC) + fp32 tanh + fp32 layer-3 accumulate, 4 batches
__device__ __forceinline__ void l23_node(const __half2* h1lo, const __half2* h1hi,
                                         unsigned int wlo, unsigned int whi,
                                         float b2o, float w3o, float4& y) {
    const __half2 bb = __half2half2(__float2half(b2o));
    __half2 slo = bb, shi = bb;
    slo = __hfma2(__low2half2(u2h(wlo)),  h1lo[0], slo);
    shi = __hfma2(__low2half2(u2h(wlo)),  h1hi[0], shi);
    slo = __hfma2(__high2half2(u2h(wlo)), h1lo[1], slo);
    shi = __hfma2(__high2half2(u2h(wlo)), h1hi[1], shi);
    slo = __hfma2(__low2half2(u2h(whi)),  h1lo[2], slo);
    shi = __hfma2(__low2half2(u2h(whi)),  h1hi[2], shi);
    slo = __hfma2(__high2half2(u2h(whi)), h1lo[3], slo);
    shi = __hfma2(__high2half2(u2h(whi)), h1hi[3], shi);
    const float2 a = __half22float2(slo);
    const float2 b = __half22float2(shi);
    y.x = fmaf(w3o, tanh_mufu(a.x), y.x);
    y.y = fmaf(w3o, tanh_mufu(a.y), y.y);
    y.z = fmaf(w3o, tanh_mufu(b.x), y.z);
    y.w = fmaf(w3o, tanh_mufu(b.y), y.w);
}

__global__ void __launch_bounds__(THREADS, 1) fused_kernel(
    const float* __restrict__ b1, const float* __restrict__ b2,
    const float* __restrict__ w3, const float* __restrict__ b3)
{
    extern __shared__ unsigned int xs[];   // [NTF][32] uint -> 128B fp16 rows
    const int tid = threadIdx.x;
    const int chunk = blockIdx.x & 1;      // 148 blocks -> 74 per chunk
    const int b0 = chunk * CHUNK;

    // fill feature slice (rows of 64 fp16 = 8 uint4)
    {
        const uint4* src = (const uint4*)g_xTh;  // global row = 16 uint4
        uint4* dst = (uint4*)xs;
#pragma unroll
        for (int i = tid; i < NTF * 8; i += THREADS) {
            const int t = i >> 3, c = i & 7;
            dst[i] = src[t * 16 + chunk * 8 + c];
        }
    }
    __syncthreads();

    const int lane = tid & 31;
    const int gl   = lane >> 4;     // gene within pair (0..1)
    const int bsub = lane & 15;     // batch quad -> batches b0+bsub*4 .. +3
    const char* fb = (const char*)xs + bsub * 8;   // lane's 4-batch column
    const int wid = (blockIdx.x >> 1) * 32 + (tid >> 5);  // 0..2367 in chunk

    for (int p = wid; p < NPAIRS; p += WARPS_PER_CHUNK) {
        const int g = p * 2 + gl;
        const uint4* ip = (const uint4*)(g_i16 + (size_t)g * 64);
        const uint4* wp = (const uint4*)(g_w1h + (size_t)g * 64);

        // ---- hoist ALL layer-2/3 metadata: latency drains under layer 1 ----
        const uint4 w2a = __ldg((const uint4*)(g_w2h + (size_t)g * 16));
        const uint4 w2b = __ldg((const uint4*)(g_w2h + (size_t)g * 16) + 1);
        const float4 b2v = __ldg((const float4*)(b2 + g * 4));
        const float4 w3v = __ldg((const float4*)(w3 + g * 4));
        const float  yb  = __ldg(b3 + g);
        const float4 b1v = __ldg((const float4*)(b1 + g * 4));
        const float bn[4] = {b1v.x, b1v.y, b1v.z, b1v.w};

        // ---------------- layer 1: 4 nodes x 16 edges ----------------
        __half2 h1lo[4], h1hi[4];
#pragma unroll
        for (int n = 0; n < 4; n++) {
            const uint4 ia = __ldg(ip + 2 * n);
            const uint4 ib = __ldg(ip + 2 * n + 1);
            const uint4 wa = __ldg(wp + 2 * n);
            const uint4 wb = __ldg(wp + 2 * n + 1);
            float4 acc = make_float4(bn[n], bn[n], bn[n], bn[n]);
            edge_group(fb, ia.x, ia.y, wa.x, wa.y, acc);
            edge_group(fb, ia.z, ia.w, wa.z, wa.w, acc);
            edge_group(fb, ib.x, ib.y, wb.x, wb.y, acc);
            edge_group(fb, ib.z, ib.w, wb.z, wb.w, acc);
            h1lo[n] = tanh_h2(make_float2(acc.x, acc.y));
            h1hi[n] = tanh_h2(make_float2(acc.z, acc.w));
        }

        // ---------------- layers 2+3 (metadata already resident) ----------
        float4 y = make_float4(yb, yb, yb, yb);
        l23_node(h1lo, h1hi, w2a.x, w2a.y, b2v.x, w3v.x, y);
        l23_node(h1lo, h1hi, w2a.z, w2a.w, b2v.y, w3v.y, y);
        l23_node(h1lo, h1hi, w2b.x, w2b.y, b2v.z, w3v.z, y);
        l23_node(h1lo, h1hi, w2b.z, w2b.w, b2v.w, w3v.w, y);

        // coalesced gene-major store (float4 per lane)
        *(float4*)&g_yT[(size_t)g * BATCH + b0 + bsub * 4] = y;
    }
}

extern "C" void kernel_launch(void* const* d_in, const int* in_sizes, int n_in,
                              void* d_out, int out_size) {
    const float* features = (const float*)d_in[0];
    const float* w1 = (const float*)d_in[1];
    const float* b1 = (const float*)d_in[2];
    const float* w2 = (const float*)d_in[3];
    const float* b2 = (const float*)d_in[4];
    const float* w3 = (const float*)d_in[5];
    const float* b3 = (const float*)d_in[6];
    const int* in1 = (const int*)d_in[8];
    float* out = (float*)d_out;

    cudaFuncSetAttribute(fused_kernel,
                         cudaFuncAttributeMaxDynamicSharedMemorySize, SMEM_BYTES);

    prep_edges<<<625, 256>>>(in1, w1);                     // launch 0
    prep_feat<<<285, 256>>>(features, w2);                 // launch 1
    fused_kernel<<<GRID, THREADS, SMEM_BYTES>>>(b1, b2, w3, b3);  // launch 2
    transpose_out<<<(NGENES / TG) * (BATCH / TB), 256>>>(out);    // launch 3
}

// round 11
// speedup vs baseline: 1.5413x; 1.5413x over previous
#include <cuda_runtime.h>
#include <cuda_fp16.h>

#define BATCH 128
#define NTF 1024
#define NGENES 20000
#define NPAIRS (NGENES / 2)      // 10000 gene-pairs
#define NEDGE1 (NGENES * 64)     // 1,280,000 layer-1 edges
#define CHUNK 64                 // batch elements per block
#define THREADS 1024             // 32 warps
#define GRID 148                 // one wave, 74 blocks per chunk
#define WARPS_PER_CHUNK 2368     // 74 blocks * 32 warps
#define SMEM_BYTES (NTF * CHUNK * 2)  // 131072

// device scratch
__device__ __half g_xTh[NTF * BATCH];        // transposed fp16 features
__device__ unsigned short g_i16[NEDGE1];     // u16 edge indices
__device__ __half g_w1h[NEDGE1];             // fp16 layer-1 weights
__device__ uint4  g_tail[NGENES * 4];        // 64B/gene: w2h + biases + w3h + b3
__device__ __half g_yTh[NGENES * BATCH];     // gene-major fp16 output

__device__ __forceinline__ unsigned int packh2(float a, float b) {
    const __half2 h = __float22half2_rn(make_float2(a, b));
    return *reinterpret_cast<const unsigned int*>(&h);
}
__device__ __forceinline__ unsigned int pack16(int a, int b) {
    return (unsigned int)a | ((unsigned int)b << 16);
}

// prep: [0,128) feature transpose; [128,753) edge tables; [753,832) tail structs
__global__ void prep_kernel(const float* __restrict__ f,
                            const float* __restrict__ w1,
                            const int*   __restrict__ in1,
                            const float* __restrict__ w2,
                            const float* __restrict__ b1,
                            const float* __restrict__ b2,
                            const float* __restrict__ w3,
                            const float* __restrict__ b3) {
    const int bid = blockIdx.x;
    if (bid < 128) {
        __shared__ float tile[32][33];
        const int tx = threadIdx.x & 31, ty = threadIdx.x >> 5;
        const int t0 = (bid & 31) * 32;   // TF base
        const int b0 = (bid >> 5) * 32;   // batch base
#pragma unroll
        for (int j = 0; j < 32; j += 8)
            tile[ty + j][tx] = f[(b0 + ty + j) * NTF + t0 + tx];
        __syncthreads();
#pragma unroll
        for (int j = 0; j < 32; j += 8)
            g_xTh[(t0 + ty + j) * BATCH + b0 + tx] = __float2half(tile[tx][ty + j]);
    } else if (bid < 753) {
        // 625*256*8 = 1,280,000 = NEDGE1 exactly
        const int e = ((bid - 128) * 256 + threadIdx.x) * 8;
        const int4 i0 = __ldg((const int4*)(in1 + e));
        const int4 i1 = __ldg((const int4*)(in1 + e) + 1);
        const float4 a0 = __ldg((const float4*)(w1 + e));
        const float4 a1 = __ldg((const float4*)(w1 + e) + 1);
        uint4 iv, wv;
        iv.x = pack16(i0.x, i0.y); iv.y = pack16(i0.z, i0.w);
        iv.z = pack16(i1.x, i1.y); iv.w = pack16(i1.z, i1.w);
        wv.x = packh2(a0.x, a0.y); wv.y = packh2(a0.z, a0.w);
        wv.z = packh2(a1.x, a1.y); wv.w = packh2(a1.z, a1.w);
        *(uint4*)(g_i16 + e) = iv;
        *(uint4*)(g_w1h + e) = wv;
    } else {
        // one gene per thread: build the 64B tail struct
        const int g = (bid - 753) * 256 + threadIdx.x;
        if (g < NGENES) {
            const float4 q0 = __ldg((const float4*)(w2 + g * 16));
            const float4 q1 = __ldg((const float4*)(w2 + g * 16) + 1);
            const float4 q2 = __ldg((const float4*)(w2 + g * 16) + 2);
            const float4 q3 = __ldg((const float4*)(w2 + g * 16) + 3);
            const float4 b1q = __ldg((const float4*)(b1 + g * 4));
            const float4 b2q = __ldg((const float4*)(b2 + g * 4));
            const float4 w3q = __ldg((const float4*)(w3 + g * 4));
            const float  b3s = __ldg(b3 + g);
            uint4 u0, u1, u2, u3;
            u0.x = packh2(q0.x, q0.y); u0.y = packh2(q0.z, q0.w);
            u0.z = packh2(q1.x, q1.y); u0.w = packh2(q1.z, q1.w);
            u1.x = packh2(q2.x, q2.y); u1.y = packh2(q2.z, q2.w);
            u1.z = packh2(q3.x, q3.y); u1.w = packh2(q3.z, q3.w);
            u2.x = packh2(b1q.x, b1q.y); u2.y = packh2(b1q.z, b1q.w);
            u2.z = packh2(b2q.x, b2q.y); u2.w = packh2(b2q.z, b2q.w);
            u3.x = packh2(w3q.x, w3q.y); u3.y = packh2(w3q.z, w3q.w);
            u3.z = __float_as_uint(b3s);  u3.w = 0u;
            uint4* dst = g_tail + (size_t)g * 4;
            dst[0] = u0; dst[1] = u1; dst[2] = u2; dst[3] = u3;
        }
    }
}

// g_yTh [NGENES][BATCH] fp16 -> out [BATCH][NGENES] fp32
__global__ void transpose_out(float* __restrict__ out) {
    __shared__ float tile[32][33];
    const int tx = threadIdx.x, ty = threadIdx.y;
    const int g0 = blockIdx.x * 32;
    const int b0 = blockIdx.y * 32;
#pragma unroll
    for (int j = 0; j < 32; j += 8)
        tile[ty + j][tx] = __half2float(g_yTh[(size_t)(g0 + ty + j) * BATCH + b0 + tx]);
    __syncthreads();
#pragma unroll
    for (int j = 0; j < 32; j += 8)
        out[(size_t)(b0 + ty + j) * NGENES + g0 + tx] = tile[tx][ty + j];
}

__device__ __forceinline__ __half2 u2h(unsigned int u) {
    return *reinterpret_cast<__half2*>(&u);
}
__device__ __forceinline__ float tanh_mufu(float x) {
    float y;
    asm("tanh.approx.f32 %0, %1;" : "=f"(y) : "f"(x));
    return y;
}
__device__ __forceinline__ __half2 tanh_h2(float2 a) {
    __half2 h = __float22half2_rn(a);
    unsigned int u = *reinterpret_cast<unsigned int*>(&h), r;
    asm("tanh.approx.f16x2 %0, %1;" : "=r"(r) : "r"(u));
    return u2h(r);
}

// 4 edges (2 packed index words), LDS.64 row gathers, fp16 chain, fp32 acc
__device__ __forceinline__ void edge_group(const char* fb, unsigned int e01,
                                           unsigned int e23, unsigned int wlo,
                                           unsigned int whi, float4& acc) {
    const uint2 x0 = *(const uint2*)(fb + ((e01 & 0xFFFFu) << 7));
    const uint2 x1 = *(const uint2*)(fb + ((e01 >> 16) << 7));
    const uint2 x2 = *(const uint2*)(fb + ((e23 & 0xFFFFu) << 7));
    const uint2 x3 = *(const uint2*)(fb + ((e23 >> 16) << 7));
    __half2 alo = __hmul2(__low2half2(u2h(wlo)),  u2h(x0.x));
    __half2 ahi = __hmul2(__low2half2(u2h(wlo)),  u2h(x0.y));
    alo = __hfma2(__high2half2(u2h(wlo)), u2h(x1.x), alo);
    ahi = __hfma2(__high2half2(u2h(wlo)), u2h(x1.y), ahi);
    alo = __hfma2(__low2half2(u2h(whi)),  u2h(x2.x), alo);
    ahi = __hfma2(__low2half2(u2h(whi)),  u2h(x2.y), ahi);
    alo = __hfma2(__high2half2(u2h(whi)), u2h(x3.x), alo);
    ahi = __hfma2(__high2half2(u2h(whi)), u2h(x3.y), ahi);
    const float2 flo = __half22float2(alo);
    const float2 fhi = __half22float2(ahi);
    acc.x += flo.x; acc.y += flo.y; acc.z += fhi.x; acc.w += fhi.y;
}

// layer-1 node: 16 edges, two independent accumulators (breaks FADD chain)
__device__ __forceinline__ void l1_node(const char* fb, uint4 ia, uint4 ib,
                                        uint4 wa, uint4 wb, float bias,
                                        __half2& hlo, __half2& hhi) {
    float4 a0 = make_float4(bias, bias, bias, bias);
    float4 a1 = make_float4(0.f, 0.f, 0.f, 0.f);
    edge_group(fb, ia.x, ia.y, wa.x, wa.y, a0);
    edge_group(fb, ia.z, ia.w, wa.z, wa.w, a1);
    edge_group(fb, ib.x, ib.y, wb.x, wb.y, a0);
    edge_group(fb, ib.z, ib.w, wb.z, wb.w, a1);
    hlo = tanh_h2(make_float2(a0.x + a1.x, a0.y + a1.y));
    hhi = tanh_h2(make_float2(a0.z + a1.z, a0.w + a1.w));
}

// layer-2 node (fp16 MAC) + fp32 tanh + fp32 layer-3 accumulate, 4 batches
__device__ __forceinline__ void l23_node(const __half2* h1lo, const __half2* h1hi,
                                         unsigned int wlo, unsigned int whi,
                                         float b2o, float w3o, float4& y) {
    const __half2 bb = __half2half2(__float2half(b2o));
    __half2 slo = bb, shi = bb;
    slo = __hfma2(__low2half2(u2h(wlo)),  h1lo[0], slo);
    shi = __hfma2(__low2half2(u2h(wlo)),  h1hi[0], shi);
    slo = __hfma2(__high2half2(u2h(wlo)), h1lo[1], slo);
    shi = __hfma2(__high2half2(u2h(wlo)), h1hi[1], shi);
    slo = __hfma2(__low2half2(u2h(whi)),  h1lo[2], slo);
    shi = __hfma2(__low2half2(u2h(whi)),  h1hi[2], shi);
    slo = __hfma2(__high2half2(u2h(whi)), h1lo[3], slo);
    shi = __hfma2(__high2half2(u2h(whi)), h1hi[3], shi);
    const float2 a = __half22float2(slo);
    const float2 b = __half22float2(shi);
    y.x = fmaf(w3o, tanh_mufu(a.x), y.x);
    y.y = fmaf(w3o, tanh_mufu(a.y), y.y);
    y.z = fmaf(w3o, tanh_mufu(b.x), y.z);
    y.w = fmaf(w3o, tanh_mufu(b.y), y.w);
}

__global__ void __launch_bounds__(THREADS, 1) fused_kernel() {
    extern __shared__ unsigned int xs[];   // [NTF][32] uint -> 128B fp16 rows
    const int tid = threadIdx.x;
    const int chunk = blockIdx.x & 1;      // 148 blocks -> 74 per chunk
    const int b0 = chunk * CHUNK;

    // fill feature slice (rows of 64 fp16 = 8 uint4)
    {
        const uint4* src = (const uint4*)g_xTh;  // global row = 16 uint4
        uint4* dst = (uint4*)xs;
#pragma unroll
        for (int i = tid; i < NTF * 8; i += THREADS) {
            const int t = i >> 3, c = i & 7;
            dst[i] = src[t * 16 + chunk * 8 + c];
        }
    }
    __syncthreads();

    const int lane = tid & 31;
    const int gl   = lane >> 4;     // gene within pair (0..1)
    const int bsub = lane & 15;     // batch quad -> batches b0+bsub*4 .. +3
    const char* fb = (const char*)xs + bsub * 8;   // lane's 4-batch column
    const int wid = (blockIdx.x >> 1) * 32 + (tid >> 5);  // 0..2367 in chunk

    for (int p = wid; p < NPAIRS; p += WARPS_PER_CHUNK) {
        const int g = p * 2 + gl;
        const uint4* ip = (const uint4*)(g_i16 + (size_t)g * 64);
        const uint4* wp = (const uint4*)(g_w1h + (size_t)g * 64);
        const uint4* tp = g_tail + (size_t)g * 4;

        // biases first (consumed during layer 1; few live regs)
        const uint4 u2 = __ldg(tp + 2);   // b1h x4, b2h x4
        const uint4 u3 = __ldg(tp + 3);   // w3h x4, b3 fp32
        const float2 b1a = __half22float2(u2h(u2.x));
        const float2 b1b = __half22float2(u2h(u2.y));

        __half2 h1lo[4], h1hi[4];
        l1_node(fb, __ldg(ip + 0), __ldg(ip + 1), __ldg(wp + 0), __ldg(wp + 1),
                b1a.x, h1lo[0], h1hi[0]);
        l1_node(fb, __ldg(ip + 2), __ldg(ip + 3), __ldg(wp + 2), __ldg(wp + 3),
                b1a.y, h1lo[1], h1hi[1]);
        // w2 loads issued mid-layer-1: latency drains under nodes 2-3
        const uint4 u0 = __ldg(tp + 0);
        const uint4 u1 = __ldg(tp + 1);
        l1_node(fb, __ldg(ip + 4), __ldg(ip + 5), __ldg(wp + 4), __ldg(wp + 5),
                b1b.x, h1lo[2], h1hi[2]);
        l1_node(fb, __ldg(ip + 6), __ldg(ip + 7), __ldg(wp + 6), __ldg(wp + 7),
                b1b.y, h1lo[3], h1hi[3]);

        // ---------------- layers 2+3 ----------------
        const float2 b2a = __half22float2(u2h(u2.z));
        const float2 b2b = __half22float2(u2h(u2.w));
        const float2 w3a = __half22float2(u2h(u3.x));
        const float2 w3b = __half22float2(u2h(u3.y));
        const float  yb  = __uint_as_float(u3.z);
        float4 y = make_float4(yb, yb, yb, yb);
        l23_node(h1lo, h1hi, u0.x, u0.y, b2a.x, w3a.x, y);
        l23_node(h1lo, h1hi, u0.z, u0.w, b2a.y, w3a.y, y);
        l23_node(h1lo, h1hi, u1.x, u1.y, b2b.x, w3b.x, y);
        l23_node(h1lo, h1hi, u1.z, u1.w, b2b.y, w3b.y, y);

        // fp16 gene-major store (8B per lane, 128B per half-warp)
        const __half2 ylo = __float22half2_rn(make_float2(y.x, y.y));
        const __half2 yhi = __float22half2_rn(make_float2(y.z, y.w));
        uint2 yy;
        yy.x = *reinterpret_cast<const unsigned int*>(&ylo);
        yy.y = *reinterpret_cast<const unsigned int*>(&yhi);
        *(uint2*)&g_yTh[(size_t)g * BATCH + b0 + bsub * 4] = yy;
    }
}

extern "C" void kernel_launch(void* const* d_in, const int* in_sizes, int n_in,
                              void* d_out, int out_size) {
    const float* features = (const float*)d_in[0];
    const float* w1 = (const float*)d_in[1];
    const float* b1 = (const float*)d_in[2];
    const float* w2 = (const float*)d_in[3];
    const float* b2 = (const float*)d_in[4];
    const float* w3 = (const float*)d_in[5];
    const float* b3 = (const float*)d_in[6];
    const int* in1 = (const int*)d_in[8];
    float* out = (float*)d_out;

    cudaFuncSetAttribute(fused_kernel,
                         cudaFuncAttributeMaxDynamicSharedMemorySize, SMEM_BYTES);

    prep_kernel<<<832, 256>>>(features, w1, in1, w2, b1, b2, w3, b3);
    fused_kernel<<<GRID, THREADS, SMEM_BYTES>>>();
    transpose_out<<<dim3(NGENES / 32, BATCH / 32), dim3(32, 8)>>>(out);
}